// round 13
// baseline (speedup 1.0000x reference)
#include <cuda_runtime.h>
#include <cstdint>

#define NV    64
#define TMAX  2048
#define EDIM  512
#define HDIM  64
#define G3    192   // 3*H
#define NCHUNK (TMAX / 64)   // 32
#define NTILE (NV * NCHUNK)  // 2048
#define NSCAN 32             // scan CTAs (2 variables each)

// ---------------- scratch ----------------
__device__ float g_xg[(size_t)NV * TMAX * G3];   // [V][T][192] x_gates (+b_ih)
__device__ float g_hT[NV * HDIM];
__device__ float g_Wt[EDIM * G3];                // W_ih transposed: [e][n]
__device__ float g_hid[64];                      // MLP hidden
__device__ volatile unsigned g_flag[NTILE];      // producer->consumer ready flags
__device__ unsigned g_mlp_ctr;

// ---------------- helpers ----------------
typedef unsigned long long ull;
__device__ __forceinline__ void ffma2(ull &d, ull a, ull b) {
    asm volatile("fma.rn.f32x2 %0, %1, %2, %0;" : "+l"(d) : "l"(a), "l"(b));
}
__device__ __forceinline__ float hsum2(ull d) {
    unsigned int a, b;
    asm("mov.b64 {%0, %1}, %2;" : "=r"(a), "=r"(b) : "l"(d));
    return __uint_as_float(a) + __uint_as_float(b);
}
__device__ __forceinline__ void unpack2(ull d, float &x, float &y) {
    unsigned int a, b;
    asm("mov.b64 {%0, %1}, %2;" : "=r"(a), "=r"(b) : "l"(d));
    x = __uint_as_float(a); y = __uint_as_float(b);
}
__device__ __forceinline__ void cp_async16(void* dst, const void* src) {
    unsigned int d = (unsigned int)__cvta_generic_to_shared(dst);
    asm volatile("cp.async.ca.shared.global [%0], [%1], 16;" :: "r"(d), "l"(src));
}
__device__ __forceinline__ float tanh_fast(float x) {
    float y;
    asm("tanh.approx.f32 %0, %1;" : "=f"(y) : "f"(x));
    return y;
}
__device__ __forceinline__ float sigmoid_fast(float x) {
    return fmaf(0.5f, tanh_fast(0.5f * x), 0.5f);
}

// =====================================================================
// Kernel 0: transpose W_ih; zero flags + counter (every launch).
// =====================================================================
__global__ __launch_bounds__(256) void transpose_wih(const float* __restrict__ W_ih)
{
    int idx = blockIdx.x * 256 + threadIdx.x;
    if (idx < EDIM * G3) {
        int e = idx / G3, n = idx - e * G3;
        g_Wt[idx] = W_ih[(size_t)n * EDIM + e];
    }
    if (blockIdx.x == 0) {
        for (int i = threadIdx.x; i < NTILE; i += 256) g_flag[i] = 0u;
        if (threadIdx.x == 0) g_mlp_ctr = 0u;
    }
}

// =====================================================================
// FUSED kernel (256 threads): bids 0..31 = scan pairs (vars bid, bid+32),
// bids 32..2079 = gemm tiles (chunk-major v-fast; threads 0..127 only).
// =====================================================================
extern __shared__ __align__(16) char g_dynsmem[];

// ---- producer tile: 64(M) x 192(N) x 32(K) double-buffered ----
__device__ void gemm_tile(int v, int tt,
                          const float* __restrict__ emb,
                          const int* __restrict__ lengths,
                          const float* __restrict__ b_ih)
{
    const int tid = threadIdx.x;
    const int len = lengths[v];
    if (tt * 64 >= len) {
        if (tid == 0) g_flag[v * NCHUNK + tt] = 1u;
        return;
    }

    float2 (*Asd)[32][64] = (float2 (*)[32][64])g_dynsmem;
    float  (*Bs)[32][192] = (float (*)[32][192])(g_dynsmem + 2 * 32 * 64 * sizeof(float2));

    const int tm = tid >> 4;
    const int tn = tid & 15;
    const int ar = tid >> 1;
    const int aq = tid & 1;
    const int kb = tid >> 2;
    const int seg = tid & 3;

    const float* Ag = emb + ((size_t)v * TMAX + (size_t)tt * 64 + ar) * EDIM + aq * 16;
    const float* Bg = g_Wt + (size_t)kb * G3 + seg * 48;

    ull acc[8][6];
#pragma unroll
    for (int i = 0; i < 8; i++)
#pragma unroll
        for (int j = 0; j < 6; j++) acc[i][j] = 0ull;

    float4 aR[4];
#pragma unroll
    for (int i = 0; i < 4; i++) aR[i] = *(const float4*)(Ag + i * 4);
#pragma unroll
    for (int i = 0; i < 12; i++)
        cp_async16(&Bs[0][kb][seg * 48 + i * 4], Bg + i * 4);
    asm volatile("cp.async.commit_group;" ::: "memory");
#pragma unroll
    for (int i = 0; i < 4; i++) {
        Asd[0][aq * 16 + i * 4 + 0][ar] = make_float2(aR[i].x, aR[i].x);
        Asd[0][aq * 16 + i * 4 + 1][ar] = make_float2(aR[i].y, aR[i].y);
        Asd[0][aq * 16 + i * 4 + 2][ar] = make_float2(aR[i].z, aR[i].z);
        Asd[0][aq * 16 + i * 4 + 3][ar] = make_float2(aR[i].w, aR[i].w);
    }
#pragma unroll
    for (int i = 0; i < 4; i++) aR[i] = *(const float4*)(Ag + 32 + i * 4);
    asm volatile("cp.async.wait_group 0;" ::: "memory");
    __syncthreads();

    for (int it = 0; it < 16; it++) {
        const int cur = it & 1, nxt = cur ^ 1;
        if (it < 15) {
            const float* bsrc = Bg + (size_t)(it + 1) * 32 * G3;
#pragma unroll
            for (int i = 0; i < 12; i++)
                cp_async16(&Bs[nxt][kb][seg * 48 + i * 4], bsrc + i * 4);
            asm volatile("cp.async.commit_group;" ::: "memory");
#pragma unroll
            for (int i = 0; i < 4; i++) {
                Asd[nxt][aq * 16 + i * 4 + 0][ar] = make_float2(aR[i].x, aR[i].x);
                Asd[nxt][aq * 16 + i * 4 + 1][ar] = make_float2(aR[i].y, aR[i].y);
                Asd[nxt][aq * 16 + i * 4 + 2][ar] = make_float2(aR[i].z, aR[i].z);
                Asd[nxt][aq * 16 + i * 4 + 3][ar] = make_float2(aR[i].w, aR[i].w);
            }
            if (it < 14) {
#pragma unroll
                for (int i = 0; i < 4; i++)
                    aR[i] = *(const float4*)(Ag + (it + 2) * 32 + i * 4);
            }
        }
#pragma unroll 4
        for (int kk = 0; kk < 32; kk++) {
            ull a8[8];
            const ull* ap = (const ull*)&Asd[cur][kk][tm * 8];
#pragma unroll
            for (int i = 0; i < 8; i++) a8[i] = ap[i];
            ull b6[6];
            const ull* bp = (const ull*)&Bs[cur][kk][tn * 12];
#pragma unroll
            for (int j = 0; j < 6; j++) b6[j] = bp[j];
#pragma unroll
            for (int i = 0; i < 8; i++)
#pragma unroll
                for (int j = 0; j < 6; j++) ffma2(acc[i][j], a8[i], b6[j]);
        }
        if (it < 15) {
            asm volatile("cp.async.wait_group 0;" ::: "memory");
            __syncthreads();
        }
    }

    float bias[12];
    *(float4*)&bias[0] = *(const float4*)(b_ih + tn * 12 + 0);
    *(float4*)&bias[4] = *(const float4*)(b_ih + tn * 12 + 4);
    *(float4*)&bias[8] = *(const float4*)(b_ih + tn * 12 + 8);
#pragma unroll
    for (int i = 0; i < 8; i++) {
        size_t row = (size_t)v * TMAX + (size_t)tt * 64 + tm * 8 + i;
        float* outp = g_xg + row * G3 + tn * 12;
        float o[12];
#pragma unroll
        for (int j = 0; j < 6; j++) {
            float x, y; unpack2(acc[i][j], x, y);
            o[2 * j]     = x + bias[2 * j];
            o[2 * j + 1] = y + bias[2 * j + 1];
        }
        *(float4*)(outp + 0) = make_float4(o[0], o[1], o[2], o[3]);
        *(float4*)(outp + 4) = make_float4(o[4], o[5], o[6], o[7]);
        *(float4*)(outp + 8) = make_float4(o[8], o[9], o[10], o[11]);
    }

    __threadfence();
    __syncthreads();
    if (tid == 0) g_flag[v * NCHUNK + tt] = 1u;
}

// ---- consumer: TWO variables per CTA; each 128-thread group runs the
// round-10 scan on its own variable. 2 independent warps/SMSP hide each
// other's LDS/shfl/MUFU latency. Shared barrier, loop to max(lenA,lenB).
__device__ void scan_pair(const int* __restrict__ lengths,
                          const float* __restrict__ W_hh,
                          const float* __restrict__ b_hh)
{
    const int tid   = threadIdx.x;
    const int group = tid >> 7;      // 0 or 1
    const int wtid  = tid & 127;
    const int v     = blockIdx.x + group * 32;
    const int lenA  = lengths[blockIdx.x];
    const int lenB  = lengths[blockIdx.x + 32];
    const int len   = group ? lenB : lenA;
    const int maxlen = lenA > lenB ? lenA : lenB;
    const int j    = wtid >> 1;
    const int half = wtid & 1;

    // smem: per-group h ping-pong + xg ring
    float (*sh_h)[2][HDIM] = (float (*)[2][HDIM])g_dynsmem;                    // [2][2][64]
    float (*sh_xg)[4][G3]  = (float (*)[4][G3])(g_dynsmem + 2 * 2 * HDIM * 4); // [2][4][192]

    ull wr[16], wz[16], wn[16];
    {
        const ull* pr = (const ull*)(W_hh + (size_t)(j)       * HDIM + half * 32);
        const ull* pz = (const ull*)(W_hh + (size_t)(64 + j)  * HDIM + half * 32);
        const ull* pn = (const ull*)(W_hh + (size_t)(128 + j) * HDIM + half * 32);
#pragma unroll
        for (int i = 0; i < 16; i++) { wr[i] = pr[i]; wz[i] = pz[i]; wn[i] = pn[i]; }
    }
    const float br = b_hh[j], bz = b_hh[64 + j], bn = b_hh[128 + j];
    float myh = 0.f;
    if (wtid < HDIM) sh_h[group][0][wtid] = 0.f;

    const float* xgbase = g_xg + (size_t)v * TMAX * G3;
    int confirmed = -1;

    if (len > 0 && wtid < 48) {
        while (g_flag[v * NCHUNK + 0] == 0u) __nanosleep(64);
        __threadfence();
        confirmed = 0;
    }
#pragma unroll
    for (int i = 0; i < 3; i++) {
        if (len > 0 && wtid < 48) {
            int row = i; if (row > len - 1) row = len - 1;
            cp_async16(&sh_xg[group][i][wtid * 4], xgbase + (size_t)row * G3 + wtid * 4);
        }
        asm volatile("cp.async.commit_group;" ::: "memory");
    }
    asm volatile("cp.async.wait_group 2;" ::: "memory");
    __syncthreads();

    for (int t = 0; t < maxlen; t++) {
        const int buf = t & 3;
        float xr = sh_xg[group][buf][j];
        float xz = sh_xg[group][buf][64 + j];
        float xn = sh_xg[group][buf][128 + j];

        const ull* hp = (const ull*)(&sh_h[group][t & 1][half * 32]);
        ull h8[16];
#pragma unroll
        for (int i = 0; i < 16; i++) h8[i] = hp[i];

        ull a0 = 0ull, a1 = 0ull;
#pragma unroll
        for (int i = 0; i < 16; i += 2) { ffma2(a0, wr[i], h8[i]); ffma2(a1, wr[i + 1], h8[i + 1]); }
        float sr = hsum2(a0) + hsum2(a1);
        sr += __shfl_xor_sync(0xffffffffu, sr, 1);

        ull c0 = 0ull, c1 = 0ull;
#pragma unroll
        for (int i = 0; i < 16; i += 2) { ffma2(c0, wz[i], h8[i]); ffma2(c1, wz[i + 1], h8[i + 1]); }
        float sz = hsum2(c0) + hsum2(c1);
        sz += __shfl_xor_sync(0xffffffffu, sz, 1);

        float rr = sigmoid_fast(xr + sr + br);

        ull e0 = 0ull, e1 = 0ull;
#pragma unroll
        for (int i = 0; i < 16; i += 2) { ffma2(e0, wn[i], h8[i]); ffma2(e1, wn[i + 1], h8[i + 1]); }
        float sn = hsum2(e0) + hsum2(e1);
        sn += __shfl_xor_sync(0xffffffffu, sn, 1);

        float zz = sigmoid_fast(xz + sz + bz);
        float pre = xn + rr * (sn + bn);
        float nn = tanh_fast(pre);
        if (t < len) myh = nn + zz * (myh - nn);   // freeze past this var's length
        if (half == 0) sh_h[group][(t + 1) & 1][j] = myh;

        // refill src=min(t+3,len-1), flag-gated at chunk crossings
        {
            int src = t + 3; if (src > len - 1) src = len - 1;
            if (len > 0 && wtid < 48) {
                int ch = src >> 6;
                if (ch > confirmed) {
                    while (g_flag[v * NCHUNK + ch] == 0u) __nanosleep(64);
                    __threadfence();
                    confirmed = ch;
                }
                cp_async16(&sh_xg[group][(t + 3) & 3][wtid * 4],
                           xgbase + (size_t)src * G3 + wtid * 4);
            }
            asm volatile("cp.async.commit_group;" ::: "memory");
        }
        asm volatile("cp.async.wait_group 2;" ::: "memory");
        __syncthreads();
    }
    asm volatile("cp.async.wait_group 0;" ::: "memory");

    if (half == 0) g_hT[v * HDIM + j] = myh;
}

__global__ __launch_bounds__(256) void fused_kernel(
    const float* __restrict__ emb, const int* __restrict__ lengths,
    const float* __restrict__ b_ih, const float* __restrict__ W_hh,
    const float* __restrict__ b_hh)
{
    if (blockIdx.x < NSCAN) {
        scan_pair(lengths, W_hh, b_hh);
    } else {
        if (threadIdx.x >= 128) return;   // gemm tile uses 128 threads
        int idx = blockIdx.x - NSCAN;     // chunk-major, v-fast
        gemm_tile(idx & 63, idx >> 6, emb, lengths, b_ih);
    }
}

// =====================================================================
// MLP: 64 blocks layer 1 + last-block layer 2 (round-10 proven).
// =====================================================================
__global__ __launch_bounds__(128) void mlp_kernel(
    const float* __restrict__ W1, const float* __restrict__ b1,
    const float* __restrict__ W2, const float* __restrict__ b2,
    float* __restrict__ out)
{
    const int i = blockIdx.x;
    const int tid = threadIdx.x;
    const int warp = tid >> 5, lane = tid & 31;
    __shared__ float red[4];
    __shared__ int is_last;

    const float* wrow = W1 + (size_t)i * (NV * HDIM);
    float s = 0.f;
#pragma unroll
    for (int it = 0; it < 8; it++) {
        int k = (it * 128 + tid) * 4;
        float4 wv = *(const float4*)(wrow + k);
        float4 hv = *(const float4*)(g_hT + k);
        s += wv.x * hv.x + wv.y * hv.y + wv.z * hv.z + wv.w * hv.w;
    }
#pragma unroll
    for (int off = 16; off; off >>= 1) s += __shfl_xor_sync(0xffffffffu, s, off);
    if (lane == 0) red[warp] = s;
    __syncthreads();
    if (tid == 0) {
        g_hid[i] = fmaxf(red[0] + red[1] + red[2] + red[3] + b1[i], 0.f);
        __threadfence();
        unsigned old = atomicAdd(&g_mlp_ctr, 1u);
        is_last = (old == 63u);
    }
    __syncthreads();
    if (is_last && tid < 32) {
        __threadfence();
        const volatile float* gh = g_hid;
        float t2 = gh[tid] * W2[tid] + gh[tid + 32] * W2[tid + 32];
#pragma unroll
        for (int off = 16; off; off >>= 1) t2 += __shfl_xor_sync(0xffffffffu, t2, off);
        if (tid == 0) out[0] = t2 + b2[0];
    }
}

// =====================================================================
extern "C" void kernel_launch(void* const* d_in, const int* in_sizes, int n_in,
                              void* d_out, int out_size)
{
    const float* emb     = (const float*)d_in[0];
    const int*   lengths = (const int*)  d_in[1];
    const float* W_ih    = (const float*)d_in[2];
    const float* W_hh    = (const float*)d_in[3];
    const float* b_ih    = (const float*)d_in[4];
    const float* b_hh    = (const float*)d_in[5];
    const float* W1      = (const float*)d_in[6];
    const float* b1      = (const float*)d_in[7];
    const float* W2      = (const float*)d_in[8];
    const float* b2      = (const float*)d_in[9];

    static int smem_set = 0;
    const int FUSED_SMEM = 2 * 32 * 64 * (int)sizeof(float2) + 2 * 32 * 192 * (int)sizeof(float);
    if (!smem_set) {
        cudaFuncSetAttribute(fused_kernel, cudaFuncAttributeMaxDynamicSharedMemorySize, FUSED_SMEM);
        smem_set = 1;
    }

    transpose_wih<<<(EDIM * G3 + 255) / 256, 256>>>(W_ih);
    fused_kernel<<<NSCAN + NTILE, 256, FUSED_SMEM>>>(emb, lengths, b_ih, W_hh, b_hh);
    mlp_kernel<<<64, 128>>>(W1, b1, W2, b2, (float*)d_out);
}

// round 14
// speedup vs baseline: 1.0191x; 1.0191x over previous
#include <cuda_runtime.h>
#include <cstdint>

#define NV    64
#define TMAX  2048
#define EDIM  512
#define HDIM  64
#define G3    192   // 3*H
#define NCHUNK (TMAX / 64)   // 32
#define NTILE (NV * NCHUNK)  // 2048
#define NSCAN 32             // scan CTAs (2 variables each)

// ---------------- scratch ----------------
__device__ float g_xg[(size_t)NV * TMAX * G3];   // [V][T][192] x_gates (+bias)
__device__ float g_hT[NV * HDIM];
__device__ float g_Wt[EDIM * G3];                // W_ih transposed: [e][n]
__device__ float g_bias[G3];                     // b_ih + (b_hh folded for r,z rows)
__device__ float g_hid[64];                      // MLP hidden
__device__ volatile unsigned g_flag[NTILE];      // producer->consumer ready flags
__device__ unsigned g_mlp_ctr;

// ---------------- helpers ----------------
typedef unsigned long long ull;
__device__ __forceinline__ void ffma2(ull &d, ull a, ull b) {
    asm volatile("fma.rn.f32x2 %0, %1, %2, %0;" : "+l"(d) : "l"(a), "l"(b));
}
__device__ __forceinline__ float hsum2(ull d) {
    unsigned int a, b;
    asm("mov.b64 {%0, %1}, %2;" : "=r"(a), "=r"(b) : "l"(d));
    return __uint_as_float(a) + __uint_as_float(b);
}
__device__ __forceinline__ void unpack2(ull d, float &x, float &y) {
    unsigned int a, b;
    asm("mov.b64 {%0, %1}, %2;" : "=r"(a), "=r"(b) : "l"(d));
    x = __uint_as_float(a); y = __uint_as_float(b);
}
__device__ __forceinline__ void cp_async16(void* dst, const void* src) {
    unsigned int d = (unsigned int)__cvta_generic_to_shared(dst);
    asm volatile("cp.async.ca.shared.global [%0], [%1], 16;" :: "r"(d), "l"(src));
}
__device__ __forceinline__ float tanh_fast(float x) {
    float y;
    asm("tanh.approx.f32 %0, %1;" : "=f"(y) : "f"(x));
    return y;
}
__device__ __forceinline__ float sigmoid_fast(float x) {
    return fmaf(0.5f, tanh_fast(0.5f * x), 0.5f);
}

// =====================================================================
// Kernel 0: transpose W_ih -> g_Wt; build folded bias; zero flags/ctr.
// =====================================================================
__global__ __launch_bounds__(256) void transpose_wih(
    const float* __restrict__ W_ih, const float* __restrict__ b_ih,
    const float* __restrict__ b_hh)
{
    int idx = blockIdx.x * 256 + threadIdx.x;
    if (idx < EDIM * G3) {
        int e = idx / G3, n = idx - e * G3;
        g_Wt[idx] = W_ih[(size_t)n * EDIM + e];
    }
    if (blockIdx.x == 0) {
        if (threadIdx.x < G3) {
            float b = b_ih[threadIdx.x];
            if (threadIdx.x < 128) b += b_hh[threadIdx.x];   // fold r,z biases
            g_bias[threadIdx.x] = b;
        }
        for (int i = threadIdx.x; i < NTILE; i += 256) g_flag[i] = 0u;
        if (threadIdx.x == 0) g_mlp_ctr = 0u;
    }
}

// =====================================================================
// FUSED kernel (256 threads, 2 CTAs/SM): bids 0..31 = scan pairs
// (vars bid, bid+32); bids 32..2079 = gemm tiles (chunk-major v-fast).
// =====================================================================
extern __shared__ __align__(16) char g_dynsmem[];

// ---- producer tile: 64(M) x 192(N) x 32(K), 256 threads, 4x12 microtile,
// double-buffered. ~95 regs/thread -> fits the 128-reg cap.
__device__ void gemm_tile(int v, int tt,
                          const float* __restrict__ emb,
                          const int* __restrict__ lengths)
{
    const int tid = threadIdx.x;
    const int len = lengths[v];
    if (tt * 64 >= len) {
        if (tid == 0) g_flag[v * NCHUNK + tt] = 1u;
        return;
    }

    float2 (*Asd)[32][64] = (float2 (*)[32][64])g_dynsmem;
    float  (*Bs)[32][192] = (float (*)[32][192])(g_dynsmem + 2 * 32 * 64 * sizeof(float2));

    const int tm = tid >> 4;        // 0..15 -> rows tm*4..+3
    const int tn = tid & 15;        // 0..15 -> cols tn*12..+11
    const int ar = tid >> 2;        // 0..63 A row
    const int aq = tid & 3;         // k-octet (8 floats)
    const int kb = tid >> 3;        // 0..31 B k-row
    const int seg = tid & 7;        // 24-float segment

    const float* Ag = emb + ((size_t)v * TMAX + (size_t)tt * 64 + ar) * EDIM + aq * 8;
    const float* Bg = g_Wt + (size_t)kb * G3 + seg * 24;

    ull acc[4][6];
#pragma unroll
    for (int i = 0; i < 4; i++)
#pragma unroll
        for (int j = 0; j < 6; j++) acc[i][j] = 0ull;

    float4 aR[2];
    // ---- prologue: stage 0 ----
    aR[0] = *(const float4*)(Ag + 0);
    aR[1] = *(const float4*)(Ag + 4);
#pragma unroll
    for (int i = 0; i < 6; i++)
        cp_async16(&Bs[0][kb][seg * 24 + i * 4], Bg + i * 4);
    asm volatile("cp.async.commit_group;" ::: "memory");
#pragma unroll
    for (int i = 0; i < 4; i++) {
        Asd[0][aq * 8 + i][ar]     = make_float2(((const float*)&aR[0])[i], ((const float*)&aR[0])[i]);
        Asd[0][aq * 8 + 4 + i][ar] = make_float2(((const float*)&aR[1])[i], ((const float*)&aR[1])[i]);
    }
    aR[0] = *(const float4*)(Ag + 32);
    aR[1] = *(const float4*)(Ag + 36);
    asm volatile("cp.async.wait_group 0;" ::: "memory");
    __syncthreads();

    for (int it = 0; it < 16; it++) {
        const int cur = it & 1, nxt = cur ^ 1;
        if (it < 15) {
            const float* bsrc = Bg + (size_t)(it + 1) * 32 * G3;
#pragma unroll
            for (int i = 0; i < 6; i++)
                cp_async16(&Bs[nxt][kb][seg * 24 + i * 4], bsrc + i * 4);
            asm volatile("cp.async.commit_group;" ::: "memory");
#pragma unroll
            for (int i = 0; i < 4; i++) {
                Asd[nxt][aq * 8 + i][ar]     = make_float2(((const float*)&aR[0])[i], ((const float*)&aR[0])[i]);
                Asd[nxt][aq * 8 + 4 + i][ar] = make_float2(((const float*)&aR[1])[i], ((const float*)&aR[1])[i]);
            }
            if (it < 14) {
                aR[0] = *(const float4*)(Ag + (it + 2) * 32);
                aR[1] = *(const float4*)(Ag + (it + 2) * 32 + 4);
            }
        }
#pragma unroll 4
        for (int kk = 0; kk < 32; kk++) {
            ull a4[4];
            const ull* ap = (const ull*)&Asd[cur][kk][tm * 4];
#pragma unroll
            for (int i = 0; i < 4; i++) a4[i] = ap[i];
            ull b6[6];
            const ull* bp = (const ull*)&Bs[cur][kk][tn * 12];
#pragma unroll
            for (int j = 0; j < 6; j++) b6[j] = bp[j];
#pragma unroll
            for (int i = 0; i < 4; i++)
#pragma unroll
                for (int j = 0; j < 6; j++) ffma2(acc[i][j], a4[i], b6[j]);
        }
        if (it < 15) {
            asm volatile("cp.async.wait_group 0;" ::: "memory");
            __syncthreads();
        }
    }

    // epilogue: +folded bias, store
    float bias[12];
    *(float4*)&bias[0] = *(const float4*)(g_bias + tn * 12 + 0);
    *(float4*)&bias[4] = *(const float4*)(g_bias + tn * 12 + 4);
    *(float4*)&bias[8] = *(const float4*)(g_bias + tn * 12 + 8);
#pragma unroll
    for (int i = 0; i < 4; i++) {
        size_t row = (size_t)v * TMAX + (size_t)tt * 64 + tm * 4 + i;
        float* outp = g_xg + row * G3 + tn * 12;
        float o[12];
#pragma unroll
        for (int j = 0; j < 6; j++) {
            float x, y; unpack2(acc[i][j], x, y);
            o[2 * j]     = x + bias[2 * j];
            o[2 * j + 1] = y + bias[2 * j + 1];
        }
        *(float4*)(outp + 0) = make_float4(o[0], o[1], o[2], o[3]);
        *(float4*)(outp + 4) = make_float4(o[4], o[5], o[6], o[7]);
        *(float4*)(outp + 8) = make_float4(o[8], o[9], o[10], o[11]);
    }

    __threadfence();
    __syncthreads();
    if (tid == 0) g_flag[v * NCHUNK + tt] = 1u;
}

// ---- consumer: two variables per CTA; each 128-thread group = round-10
// scan on its own variable. 2 independent recurrences per SMSP hide each
// other's LDS/shfl/MUFU latency. r,z biases pre-folded into xg.
__device__ void scan_pair(const int* __restrict__ lengths,
                          const float* __restrict__ W_hh,
                          const float* __restrict__ b_hh)
{
    const int tid   = threadIdx.x;
    const int group = tid >> 7;      // 0 or 1
    const int wtid  = tid & 127;
    const int v     = blockIdx.x + group * 32;
    const int lenA  = lengths[blockIdx.x];
    const int lenB  = lengths[blockIdx.x + 32];
    const int len   = group ? lenB : lenA;
    const int maxlen = lenA > lenB ? lenA : lenB;
    const int j    = wtid >> 1;
    const int half = wtid & 1;

    float (*sh_h)[2][HDIM] = (float (*)[2][HDIM])g_dynsmem;                    // [2][2][64]
    float (*sh_xg)[4][G3]  = (float (*)[4][G3])(g_dynsmem + 2 * 2 * HDIM * 4); // [2][4][192]

    ull wr[16], wz[16], wn[16];
    {
        const ull* pr = (const ull*)(W_hh + (size_t)(j)       * HDIM + half * 32);
        const ull* pz = (const ull*)(W_hh + (size_t)(64 + j)  * HDIM + half * 32);
        const ull* pn = (const ull*)(W_hh + (size_t)(128 + j) * HDIM + half * 32);
#pragma unroll
        for (int i = 0; i < 16; i++) { wr[i] = pr[i]; wz[i] = pz[i]; wn[i] = pn[i]; }
    }
    const float bn = b_hh[128 + j];
    float myh = 0.f;
    if (wtid < HDIM) sh_h[group][0][wtid] = 0.f;

    const float* xgbase = g_xg + (size_t)v * TMAX * G3;
    int confirmed = -1;

    if (len > 0 && wtid < 48) {
        while (g_flag[v * NCHUNK + 0] == 0u) __nanosleep(64);
        __threadfence();
        confirmed = 0;
    }
#pragma unroll
    for (int i = 0; i < 3; i++) {
        if (len > 0 && wtid < 48) {
            int row = i; if (row > len - 1) row = len - 1;
            cp_async16(&sh_xg[group][i][wtid * 4], xgbase + (size_t)row * G3 + wtid * 4);
        }
        asm volatile("cp.async.commit_group;" ::: "memory");
    }
    asm volatile("cp.async.wait_group 2;" ::: "memory");
    __syncthreads();

    for (int t = 0; t < maxlen; t++) {
        const int buf = t & 3;
        float xr = sh_xg[group][buf][j];
        float xz = sh_xg[group][buf][64 + j];
        float xn = sh_xg[group][buf][128 + j];

        // matvec over my 32-wide half: single acc chain per gate,
        // h loaded in two 8-ull chunks (register diet for the 128 cap)
        const ull* hp = (const ull*)(&sh_h[group][t & 1][half * 32]);
        ull a0 = 0ull, c0 = 0ull, e0 = 0ull;
#pragma unroll
        for (int ch = 0; ch < 2; ch++) {
            ull h8[8];
#pragma unroll
            for (int i = 0; i < 8; i++) h8[i] = hp[ch * 8 + i];
#pragma unroll
            for (int i = 0; i < 8; i++) {
                ffma2(a0, wr[ch * 8 + i], h8[i]);
                ffma2(c0, wz[ch * 8 + i], h8[i]);
                ffma2(e0, wn[ch * 8 + i], h8[i]);
            }
        }
        float sr = hsum2(a0);
        sr += __shfl_xor_sync(0xffffffffu, sr, 1);
        float sz = hsum2(c0);
        sz += __shfl_xor_sync(0xffffffffu, sz, 1);

        float rr = sigmoid_fast(xr + sr);           // b_hh(r) folded into xr

        float sn = hsum2(e0);
        sn += __shfl_xor_sync(0xffffffffu, sn, 1);

        float zz = sigmoid_fast(xz + sz);           // b_hh(z) folded into xz
        float pre = xn + rr * (sn + bn);
        float nn = tanh_fast(pre);
        if (t < len) myh = nn + zz * (myh - nn);    // freeze past this var's length
        if (half == 0) sh_h[group][(t + 1) & 1][j] = myh;

        // refill src=min(t+3,len-1), flag-gated at chunk crossings
        {
            int src = t + 3; if (src > len - 1) src = len - 1;
            if (len > 0 && wtid < 48) {
                int ch = src >> 6;
                if (ch > confirmed) {
                    while (g_flag[v * NCHUNK + ch] == 0u) __nanosleep(64);
                    __threadfence();
                    confirmed = ch;
                }
                cp_async16(&sh_xg[group][(t + 3) & 3][wtid * 4],
                           xgbase + (size_t)src * G3 + wtid * 4);
            }
            asm volatile("cp.async.commit_group;" ::: "memory");
        }
        asm volatile("cp.async.wait_group 2;" ::: "memory");
        __syncthreads();
    }
    asm volatile("cp.async.wait_group 0;" ::: "memory");

    if (half == 0) g_hT[v * HDIM + j] = myh;
}

__global__ __launch_bounds__(256, 2) void fused_kernel(
    const float* __restrict__ emb, const int* __restrict__ lengths,
    const float* __restrict__ W_hh, const float* __restrict__ b_hh)
{
    if (blockIdx.x < NSCAN) {
        scan_pair(lengths, W_hh, b_hh);
    } else {
        int idx = blockIdx.x - NSCAN;     // chunk-major, v-fast
        gemm_tile(idx & 63, idx >> 6, emb, lengths);
    }
}

// =====================================================================
// MLP: 64 blocks layer 1 + last-block layer 2 (round-10 proven).
// =====================================================================
__global__ __launch_bounds__(128) void mlp_kernel(
    const float* __restrict__ W1, const float* __restrict__ b1,
    const float* __restrict__ W2, const float* __restrict__ b2,
    float* __restrict__ out)
{
    const int i = blockIdx.x;
    const int tid = threadIdx.x;
    const int warp = tid >> 5, lane = tid & 31;
    __shared__ float red[4];
    __shared__ int is_last;

    const float* wrow = W1 + (size_t)i * (NV * HDIM);
    float s = 0.f;
#pragma unroll
    for (int it = 0; it < 8; it++) {
        int k = (it * 128 + tid) * 4;
        float4 wv = *(const float4*)(wrow + k);
        float4 hv = *(const float4*)(g_hT + k);
        s += wv.x * hv.x + wv.y * hv.y + wv.z * hv.z + wv.w * hv.w;
    }
#pragma unroll
    for (int off = 16; off; off >>= 1) s += __shfl_xor_sync(0xffffffffu, s, off);
    if (lane == 0) red[warp] = s;
    __syncthreads();
    if (tid == 0) {
        g_hid[i] = fmaxf(red[0] + red[1] + red[2] + red[3] + b1[i], 0.f);
        __threadfence();
        unsigned old = atomicAdd(&g_mlp_ctr, 1u);
        is_last = (old == 63u);
    }
    __syncthreads();
    if (is_last && tid < 32) {
        __threadfence();
        const volatile float* gh = g_hid;
        float t2 = gh[tid] * W2[tid] + gh[tid + 32] * W2[tid + 32];
#pragma unroll
        for (int off = 16; off; off >>= 1) t2 += __shfl_xor_sync(0xffffffffu, t2, off);
        if (tid == 0) out[0] = t2 + b2[0];
    }
}

// =====================================================================
extern "C" void kernel_launch(void* const* d_in, const int* in_sizes, int n_in,
                              void* d_out, int out_size)
{
    const float* emb     = (const float*)d_in[0];
    const int*   lengths = (const int*)  d_in[1];
    const float* W_ih    = (const float*)d_in[2];
    const float* W_hh    = (const float*)d_in[3];
    const float* b_ih    = (const float*)d_in[4];
    const float* b_hh    = (const float*)d_in[5];
    const float* W1      = (const float*)d_in[6];
    const float* b1      = (const float*)d_in[7];
    const float* W2      = (const float*)d_in[8];
    const float* b2      = (const float*)d_in[9];

    static int smem_set = 0;
    const int FUSED_SMEM = 2 * 32 * 64 * (int)sizeof(float2) + 2 * 32 * 192 * (int)sizeof(float);
    if (!smem_set) {
        cudaFuncSetAttribute(fused_kernel, cudaFuncAttributeMaxDynamicSharedMemorySize, FUSED_SMEM);
        smem_set = 1;
    }

    transpose_wih<<<(EDIM * G3 + 255) / 256, 256>>>(W_ih, b_ih, b_hh);
    fused_kernel<<<NSCAN + NTILE, 256, FUSED_SMEM>>>(emb, lengths, W_hh, b_hh);
    mlp_kernel<<<64, 128>>>(W1, b1, W2, b2, (float*)d_out);
}

// round 15
// speedup vs baseline: 1.5317x; 1.5029x over previous
#include <cuda_runtime.h>
#include <cstdint>

#define NV    64
#define TMAX  2048
#define EDIM  512
#define HDIM  64
#define G3    192   // 3*H
#define NCHUNK (TMAX / 64)   // 32
#define NTILE (NV * NCHUNK)  // 2048

// ---------------- scratch ----------------
__device__ float g_xg[(size_t)NV * TMAX * G3];   // [V][T][192] x_gates (+folded bias)
__device__ float g_hT[NV * HDIM];
__device__ float g_Wt[EDIM * G3];                // W_ih transposed: [e][n]
__device__ float g_bias[G3];                     // b_ih + (b_hh folded for r,z rows)
__device__ float g_hid[64];                      // MLP hidden
__device__ volatile unsigned g_flag[NTILE];      // producer->consumer ready flags
__device__ unsigned g_mlp_ctr;

// ---------------- helpers ----------------
typedef unsigned long long ull;
__device__ __forceinline__ void ffma2(ull &d, ull a, ull b) {
    asm volatile("fma.rn.f32x2 %0, %1, %2, %0;" : "+l"(d) : "l"(a), "l"(b));
}
__device__ __forceinline__ float hsum2(ull d) {
    unsigned int a, b;
    asm("mov.b64 {%0, %1}, %2;" : "=r"(a), "=r"(b) : "l"(d));
    return __uint_as_float(a) + __uint_as_float(b);
}
__device__ __forceinline__ void unpack2(ull d, float &x, float &y) {
    unsigned int a, b;
    asm("mov.b64 {%0, %1}, %2;" : "=r"(a), "=r"(b) : "l"(d));
    x = __uint_as_float(a); y = __uint_as_float(b);
}
__device__ __forceinline__ void cp_async16(void* dst, const void* src) {
    unsigned int d = (unsigned int)__cvta_generic_to_shared(dst);
    asm volatile("cp.async.ca.shared.global [%0], [%1], 16;" :: "r"(d), "l"(src));
}
__device__ __forceinline__ float tanh_fast(float x) {
    float y;
    asm("tanh.approx.f32 %0, %1;" : "=f"(y) : "f"(x));
    return y;
}
__device__ __forceinline__ float sigmoid_fast(float x) {
    return fmaf(0.5f, tanh_fast(0.5f * x), 0.5f);
}

// =====================================================================
// Kernel 0: transpose W_ih -> g_Wt; build folded bias; zero flags/ctr.
// =====================================================================
__global__ __launch_bounds__(256) void transpose_wih(
    const float* __restrict__ W_ih, const float* __restrict__ b_ih,
    const float* __restrict__ b_hh)
{
    int idx = blockIdx.x * 256 + threadIdx.x;
    if (idx < EDIM * G3) {
        int e = idx / G3, n = idx - e * G3;
        g_Wt[idx] = W_ih[(size_t)n * EDIM + e];
    }
    if (blockIdx.x == 0) {
        if (threadIdx.x < G3) {
            float b = b_ih[threadIdx.x];
            if (threadIdx.x < 128) b += b_hh[threadIdx.x];   // fold r,z biases
            g_bias[threadIdx.x] = b;
        }
        for (int i = threadIdx.x; i < NTILE; i += 256) g_flag[i] = 0u;
        if (threadIdx.x == 0) g_mlp_ctr = 0u;
    }
}

// =====================================================================
// FUSED kernel (128 threads, 2 CTAs/SM — round-10 proven structure):
// bids 0..63 = scan consumers, bids 64..2111 = gemm producers
// (chunk-major, v-fast).
// =====================================================================
extern __shared__ __align__(16) char g_dynsmem[];

// ---- producer: 64(M) x 192(N) x 32(K) double-buffered, 8x12 microtile ----
__device__ void gemm_role(int v, int tt,
                          const float* __restrict__ emb,
                          const int* __restrict__ lengths)
{
    const int tid = threadIdx.x;
    const int len = lengths[v];
    if (tt * 64 >= len) {
        if (tid == 0) g_flag[v * NCHUNK + tt] = 1u;
        return;
    }

    float2 (*Asd)[32][64] = (float2 (*)[32][64])g_dynsmem;
    float  (*Bs)[32][192] = (float (*)[32][192])(g_dynsmem + 2 * 32 * 64 * sizeof(float2));

    const int tm = tid >> 4;
    const int tn = tid & 15;
    const int ar = tid >> 1;
    const int aq = tid & 1;
    const int kb = tid >> 2;
    const int seg = tid & 3;

    const float* Ag = emb + ((size_t)v * TMAX + (size_t)tt * 64 + ar) * EDIM + aq * 16;
    const float* Bg = g_Wt + (size_t)kb * G3 + seg * 48;

    ull acc[8][6];
#pragma unroll
    for (int i = 0; i < 8; i++)
#pragma unroll
        for (int j = 0; j < 6; j++) acc[i][j] = 0ull;

    float4 aR[4];
#pragma unroll
    for (int i = 0; i < 4; i++) aR[i] = *(const float4*)(Ag + i * 4);
#pragma unroll
    for (int i = 0; i < 12; i++)
        cp_async16(&Bs[0][kb][seg * 48 + i * 4], Bg + i * 4);
    asm volatile("cp.async.commit_group;" ::: "memory");
#pragma unroll
    for (int i = 0; i < 4; i++) {
        Asd[0][aq * 16 + i * 4 + 0][ar] = make_float2(aR[i].x, aR[i].x);
        Asd[0][aq * 16 + i * 4 + 1][ar] = make_float2(aR[i].y, aR[i].y);
        Asd[0][aq * 16 + i * 4 + 2][ar] = make_float2(aR[i].z, aR[i].z);
        Asd[0][aq * 16 + i * 4 + 3][ar] = make_float2(aR[i].w, aR[i].w);
    }
#pragma unroll
    for (int i = 0; i < 4; i++) aR[i] = *(const float4*)(Ag + 32 + i * 4);
    asm volatile("cp.async.wait_group 0;" ::: "memory");
    __syncthreads();

    for (int it = 0; it < 16; it++) {
        const int cur = it & 1, nxt = cur ^ 1;
        if (it < 15) {
            const float* bsrc = Bg + (size_t)(it + 1) * 32 * G3;
#pragma unroll
            for (int i = 0; i < 12; i++)
                cp_async16(&Bs[nxt][kb][seg * 48 + i * 4], bsrc + i * 4);
            asm volatile("cp.async.commit_group;" ::: "memory");
#pragma unroll
            for (int i = 0; i < 4; i++) {
                Asd[nxt][aq * 16 + i * 4 + 0][ar] = make_float2(aR[i].x, aR[i].x);
                Asd[nxt][aq * 16 + i * 4 + 1][ar] = make_float2(aR[i].y, aR[i].y);
                Asd[nxt][aq * 16 + i * 4 + 2][ar] = make_float2(aR[i].z, aR[i].z);
                Asd[nxt][aq * 16 + i * 4 + 3][ar] = make_float2(aR[i].w, aR[i].w);
            }
            if (it < 14) {
#pragma unroll
                for (int i = 0; i < 4; i++)
                    aR[i] = *(const float4*)(Ag + (it + 2) * 32 + i * 4);
            }
        }
#pragma unroll 4
        for (int kk = 0; kk < 32; kk++) {
            ull a8[8];
            const ull* ap = (const ull*)&Asd[cur][kk][tm * 8];
#pragma unroll
            for (int i = 0; i < 8; i++) a8[i] = ap[i];
            ull b6[6];
            const ull* bp = (const ull*)&Bs[cur][kk][tn * 12];
#pragma unroll
            for (int j = 0; j < 6; j++) b6[j] = bp[j];
#pragma unroll
            for (int i = 0; i < 8; i++)
#pragma unroll
                for (int j = 0; j < 6; j++) ffma2(acc[i][j], a8[i], b6[j]);
        }
        if (it < 15) {
            asm volatile("cp.async.wait_group 0;" ::: "memory");
            __syncthreads();
        }
    }

    float bias[12];
    *(float4*)&bias[0] = *(const float4*)(g_bias + tn * 12 + 0);
    *(float4*)&bias[4] = *(const float4*)(g_bias + tn * 12 + 4);
    *(float4*)&bias[8] = *(const float4*)(g_bias + tn * 12 + 8);
#pragma unroll
    for (int i = 0; i < 8; i++) {
        size_t row = (size_t)v * TMAX + (size_t)tt * 64 + tm * 8 + i;
        float* outp = g_xg + row * G3 + tn * 12;
        float o[12];
#pragma unroll
        for (int j = 0; j < 6; j++) {
            float x, y; unpack2(acc[i][j], x, y);
            o[2 * j]     = x + bias[2 * j];
            o[2 * j + 1] = y + bias[2 * j + 1];
        }
        *(float4*)(outp + 0) = make_float4(o[0], o[1], o[2], o[3]);
        *(float4*)(outp + 4) = make_float4(o[4], o[5], o[6], o[7]);
        *(float4*)(outp + 8) = make_float4(o[8], o[9], o[10], o[11]);
    }

    __threadfence();
    __syncthreads();
    if (tid == 0) g_flag[v * NCHUNK + tt] = 1u;
}

// ---- consumer: round-10 scan (single variable, 128 threads), with
// r,z biases pre-folded into xg (removes 2 FADDs from the gate chain).
__device__ void scan_role(int v,
                          const int* __restrict__ lengths,
                          const float* __restrict__ W_hh,
                          const float* __restrict__ b_hh)
{
    const int len = lengths[v];
    const int tid = threadIdx.x;
    const int j    = tid >> 1;
    const int half = tid & 1;

    float (*sh_h)[HDIM] = (float (*)[HDIM])g_dynsmem;                 // [2][64]
    float (*sh_xg)[G3]  = (float (*)[G3])(g_dynsmem + 2 * HDIM * 4);  // [4][192]

    ull wr[16], wz[16], wn[16];
    {
        const ull* pr = (const ull*)(W_hh + (size_t)(j)       * HDIM + half * 32);
        const ull* pz = (const ull*)(W_hh + (size_t)(64 + j)  * HDIM + half * 32);
        const ull* pn = (const ull*)(W_hh + (size_t)(128 + j) * HDIM + half * 32);
#pragma unroll
        for (int i = 0; i < 16; i++) { wr[i] = pr[i]; wz[i] = pz[i]; wn[i] = pn[i]; }
    }
    const float bn = b_hh[128 + j];   // only the n-gate b_hh survives (inside r*( ))
    float myh = 0.f;
    if (tid < HDIM) sh_h[0][tid] = 0.f;

    const float* xgbase = g_xg + (size_t)v * TMAX * G3;
    int confirmed = -1;

    if (len > 0) {
        if (tid < 48) {
            while (g_flag[v * NCHUNK + 0] == 0u) __nanosleep(64);
            __threadfence();
            confirmed = 0;
        }
#pragma unroll
        for (int i = 0; i < 3; i++) {
            int row = i; if (row > len - 1) row = len - 1;
            if (tid < 48)
                cp_async16(&sh_xg[i][tid * 4], xgbase + (size_t)row * G3 + tid * 4);
            asm volatile("cp.async.commit_group;" ::: "memory");
        }
        asm volatile("cp.async.wait_group 2;" ::: "memory");
    }
    __syncthreads();

    for (int t = 0; t < len; t++) {
        const int buf = t & 3;
        float xr = sh_xg[buf][j];
        float xz = sh_xg[buf][64 + j];
        float xn = sh_xg[buf][128 + j];

        const ull* hp = (const ull*)(&sh_h[t & 1][half * 32]);
        ull h8[16];
#pragma unroll
        for (int i = 0; i < 16; i++) h8[i] = hp[i];

        ull a0 = 0ull, a1 = 0ull;
#pragma unroll
        for (int i = 0; i < 16; i += 2) { ffma2(a0, wr[i], h8[i]); ffma2(a1, wr[i + 1], h8[i + 1]); }
        float sr = hsum2(a0) + hsum2(a1);
        sr += __shfl_xor_sync(0xffffffffu, sr, 1);

        ull c0 = 0ull, c1 = 0ull;
#pragma unroll
        for (int i = 0; i < 16; i += 2) { ffma2(c0, wz[i], h8[i]); ffma2(c1, wz[i + 1], h8[i + 1]); }
        float sz = hsum2(c0) + hsum2(c1);
        sz += __shfl_xor_sync(0xffffffffu, sz, 1);

        float rr = sigmoid_fast(xr + sr);           // b_hh(r) folded into xr

        ull e0 = 0ull, e1 = 0ull;
#pragma unroll
        for (int i = 0; i < 16; i += 2) { ffma2(e0, wn[i], h8[i]); ffma2(e1, wn[i + 1], h8[i + 1]); }
        float sn = hsum2(e0) + hsum2(e1);
        sn += __shfl_xor_sync(0xffffffffu, sn, 1);

        float zz = sigmoid_fast(xz + sz);           // b_hh(z) folded into xz
        float pre = xn + rr * (sn + bn);
        float nn = tanh_fast(pre);
        myh = nn + zz * (myh - nn);
        if (half == 0) sh_h[(t + 1) & 1][j] = myh;

        {
            int src = t + 3; if (src > len - 1) src = len - 1;
            if (tid < 48) {
                int ch = src >> 6;
                if (ch > confirmed) {
                    while (g_flag[v * NCHUNK + ch] == 0u) __nanosleep(64);
                    __threadfence();
                    confirmed = ch;
                }
                cp_async16(&sh_xg[(t + 3) & 3][tid * 4],
                           xgbase + (size_t)src * G3 + tid * 4);
            }
            asm volatile("cp.async.commit_group;" ::: "memory");
        }
        asm volatile("cp.async.wait_group 2;" ::: "memory");
        __syncthreads();
    }
    asm volatile("cp.async.wait_group 0;" ::: "memory");

    if (half == 0) g_hT[v * HDIM + j] = myh;
}

__global__ __launch_bounds__(128, 2) void fused_kernel(
    const float* __restrict__ emb, const int* __restrict__ lengths,
    const float* __restrict__ W_hh, const float* __restrict__ b_hh)
{
    if (blockIdx.x < NV) {
        scan_role(blockIdx.x, lengths, W_hh, b_hh);
    } else {
        int idx = blockIdx.x - NV;   // chunk-major, v-fast
        gemm_role(idx & 63, idx >> 6, emb, lengths);
    }
}

// =====================================================================
// MLP: 64 blocks layer 1 + last-block layer 2 (round-10 proven).
// =====================================================================
__global__ __launch_bounds__(128) void mlp_kernel(
    const float* __restrict__ W1, const float* __restrict__ b1,
    const float* __restrict__ W2, const float* __restrict__ b2,
    float* __restrict__ out)
{
    const int i = blockIdx.x;
    const int tid = threadIdx.x;
    const int warp = tid >> 5, lane = tid & 31;
    __shared__ float red[4];
    __shared__ int is_last;

    const float* wrow = W1 + (size_t)i * (NV * HDIM);
    float s = 0.f;
#pragma unroll
    for (int it = 0; it < 8; it++) {
        int k = (it * 128 + tid) * 4;
        float4 wv = *(const float4*)(wrow + k);
        float4 hv = *(const float4*)(g_hT + k);
        s += wv.x * hv.x + wv.y * hv.y + wv.z * hv.z + wv.w * hv.w;
    }
#pragma unroll
    for (int off = 16; off; off >>= 1) s += __shfl_xor_sync(0xffffffffu, s, off);
    if (lane == 0) red[warp] = s;
    __syncthreads();
    if (tid == 0) {
        g_hid[i] = fmaxf(red[0] + red[1] + red[2] + red[3] + b1[i], 0.f);
        __threadfence();
        unsigned old = atomicAdd(&g_mlp_ctr, 1u);
        is_last = (old == 63u);
    }
    __syncthreads();
    if (is_last && tid < 32) {
        __threadfence();
        const volatile float* gh = g_hid;
        float t2 = gh[tid] * W2[tid] + gh[tid + 32] * W2[tid + 32];
#pragma unroll
        for (int off = 16; off; off >>= 1) t2 += __shfl_xor_sync(0xffffffffu, t2, off);
        if (tid == 0) out[0] = t2 + b2[0];
    }
}

// =====================================================================
extern "C" void kernel_launch(void* const* d_in, const int* in_sizes, int n_in,
                              void* d_out, int out_size)
{
    const float* emb     = (const float*)d_in[0];
    const int*   lengths = (const int*)  d_in[1];
    const float* W_ih    = (const float*)d_in[2];
    const float* W_hh    = (const float*)d_in[3];
    const float* b_ih    = (const float*)d_in[4];
    const float* b_hh    = (const float*)d_in[5];
    const float* W1      = (const float*)d_in[6];
    const float* b1      = (const float*)d_in[7];
    const float* W2      = (const float*)d_in[8];
    const float* b2      = (const float*)d_in[9];

    static int smem_set = 0;
    const int FUSED_SMEM = 2 * 32 * 64 * (int)sizeof(float2) + 2 * 32 * 192 * (int)sizeof(float);
    if (!smem_set) {
        cudaFuncSetAttribute(fused_kernel, cudaFuncAttributeMaxDynamicSharedMemorySize, FUSED_SMEM);
        smem_set = 1;
    }

    transpose_wih<<<(EDIM * G3 + 255) / 256, 256>>>(W_ih, b_ih, b_hh);
    fused_kernel<<<NV + NTILE, 128, FUSED_SMEM>>>(emb, lengths, W_hh, b_hh);
    mlp_kernel<<<64, 128>>>(W1, b1, W2, b2, (float*)d_out);
}